// round 1
// baseline (speedup 1.0000x reference)
#include <cuda_runtime.h>
#include <cuda_bf16.h>
#include <cstdint>

#define NPITCH 226
#define KW     1537
#define NFFT   1536
#define HOP    384
#define PADL   768
#define TFRM   497
#define XLEN   192000
#define NFRAMES (2 * TFRM)

// Scratch for extracted sparse taps of conv_w (at most 3 nonzeros per row).
__device__ int   g_cnt[NPITCH];
__device__ float g_val[NPITCH][4];
__device__ int   g_pos[NPITCH][4];

// Extract nonzero taps from conv_w. One thread per element; order of taps
// within a row is irrelevant (sum is commutative).
__global__ void scan_taps_kernel(const float* __restrict__ w) {
    int i = blockIdx.x * blockDim.x + threadIdx.x;
    if (i >= NPITCH * KW) return;
    float v = w[i];
    if (v != 0.0f) {
        int row = i / KW;
        int pos = i - row * KW;
        int slot = atomicAdd(&g_cnt[row], 1);
        if (slot < 4) {
            g_val[row][slot] = v;
            g_pos[row][slot] = pos;
        }
    }
}

// One block per (b, t) frame. 384 threads x 4 outputs = 1536 outputs.
// out[b,t,l] = win[l] * sum_j val_j * x[b, t*HOP - PADL + pos_j + l]
__global__ __launch_bounds__(384)
void comb_main_kernel(const float* __restrict__ x,
                      const int*   __restrict__ pitch,
                      float*       __restrict__ out) {
    const int frame = blockIdx.x;          // 0 .. NFRAMES-1  (= b*TFRM + t)
    const int b = frame / TFRM;
    const int t = frame - b * TFRM;

    const int f   = pitch[frame];          // selected filter row
    const int cnt = g_cnt[f];

    float vals[4];
    int   poss[4];
#pragma unroll
    for (int j = 0; j < 4; j++) {
        vals[j] = (j < cnt) ? g_val[f][j] : 0.0f;
        poss[j] = (j < cnt) ? g_pos[f][j] : 0;
    }

    const float* xb   = x + (size_t)b * XLEN;
    const int    base = t * HOP - PADL;
    float*       ob   = out + (size_t)frame * NFFT;

    const int l0 = threadIdx.x * 4;        // 384*4 == 1536 exactly

    float acc[4] = {0.0f, 0.0f, 0.0f, 0.0f};
#pragma unroll
    for (int j = 0; j < 4; j++) {
        const int p = base + poss[j] + l0;
#pragma unroll
        for (int u = 0; u < 4; u++) {
            const int idx = p + u;
            const float xv = (idx >= 0 && idx < XLEN) ? __ldg(xb + idx) : 0.0f;
            acc[u] = fmaf(vals[j], xv, acc[u]);
        }
    }

#pragma unroll
    for (int u = 0; u < 4; u++) {
        // window[l] = 0.5 - 0.5*cos(2*pi*l/NFFT) = 0.5 - 0.5*cos(pi * l/768)
        const float wl = 0.5f - 0.5f * cospif((float)(l0 + u) * (1.0f / 768.0f));
        acc[u] *= wl;
    }

    *reinterpret_cast<float4*>(ob + l0) =
        make_float4(acc[0], acc[1], acc[2], acc[3]);
}

extern "C" void kernel_launch(void* const* d_in, const int* in_sizes, int n_in,
                              void* d_out, int out_size) {
    const float* x      = (const float*)d_in[0];   // (2, 192000) f32
    const int*   pitch  = (const int*)  d_in[1];   // (2, 497)    i32
    const float* conv_w = (const float*)d_in[2];   // (226, 1537) f32
    float*       out    = (float*)d_out;           // (2,497,1536,1) f32

    void* cnt_ptr = nullptr;
    cudaGetSymbolAddress(&cnt_ptr, g_cnt);
    cudaMemsetAsync(cnt_ptr, 0, sizeof(int) * NPITCH);

    const int total = NPITCH * KW;
    scan_taps_kernel<<<(total + 255) / 256, 256>>>(conv_w);

    comb_main_kernel<<<NFRAMES, 384>>>(x, pitch, out);
}